// round 4
// baseline (speedup 1.0000x reference)
#include <cuda_runtime.h>
#include <math.h>

// ---------------- problem constants ----------------
#define B_    256
#define T_    100
#define INF   227          // IN_F == OUT_F
#define HID_  1024
#define NG    4096         // 4*HID
#define K1    1251         // 227 + 1024 (layer1 K)
#define K1P   1256         // padded to multiple of 8
#define K2    2048         // 1024 + 1024 (layer2/3 K)
#define SL    (B_*HID_)    // 262144 elements per state buffer

// ---------------- static device scratch (allocation-free rule) ----------------
// Weights reordered so gate columns (i,f,g,o) of hidden unit j sit at n = 4*j + g,
// stored K-major (B[k][n]) for coalesced GEMM B loads.
__device__ float g_B1t[(size_t)K1P * NG];   // layer1: [x(227) | h0(1024)] rows, zero-padded
__device__ float g_B2 [(size_t)K2  * NG];   // layer2: [h0 | h1]
__device__ float g_B3 [(size_t)K2  * NG];   // layer3: [h1 | h2]
__device__ float g_bias[3][NG];             // bih+bhh, reordered
__device__ float g_Bd [(size_t)HID_ * INF]; // Wd^T : [k][o]
__device__ float g_h  [2][3][SL];           // ping-pong h states (slot [*][2] unused)
__device__ float g_c  [3][SL];              // cell states (updated in place)
__device__ float g_hist[(size_t)T_ * SL];   // h2 history (feeds layer3 recurrence + dense)
__device__ float g_prev[B_ * INF];          // previous out_frame (free-run input)
__device__ float g_zero[SL];                // stays zero forever (t=0 h2_old)

__device__ __forceinline__ float sigmoidf_(float x) { return 1.0f / (1.0f + expf(-x)); }

// ---------------- setup: zero mutable state each replay ----------------
__global__ void k_zero() {
    size_t N = (size_t)9 * SL; // 6*SL of g_h + 3*SL of g_c
    for (size_t i = (size_t)blockIdx.x * blockDim.x + threadIdx.x; i < N;
         i += (size_t)gridDim.x * blockDim.x) {
        if (i < (size_t)6 * SL) ((float*)g_h)[i] = 0.0f;
        else                    ((float*)g_c)[i - (size_t)6 * SL] = 0.0f;
    }
}

// ---------------- setup: reorder/transposed weight tensors ----------------
__global__ void k_setup(const float* __restrict__ Wih1, const float* __restrict__ Whh1,
                        const float* __restrict__ Wih2, const float* __restrict__ Whh2,
                        const float* __restrict__ Wih3, const float* __restrict__ Whh3,
                        const float* __restrict__ bih1, const float* __restrict__ bhh1,
                        const float* __restrict__ bih2, const float* __restrict__ bhh2,
                        const float* __restrict__ bih3, const float* __restrict__ bhh3,
                        const float* __restrict__ Wd) {
    const long S1 = (long)K1P * NG;
    const long S2 = (long)K2  * NG;
    const long S4 = (long)HID_ * INF;
    const long S5 = 3L * NG;
    const long TOT = S1 + 2 * S2 + S4 + S5;
    for (long idx = (long)blockIdx.x * blockDim.x + threadIdx.x; idx < TOT;
         idx += (long)gridDim.x * blockDim.x) {
        long r = idx;
        if (r < S1) {
            int k = (int)(r / NG), n = (int)(r % NG);
            int R = (n & 3) * HID_ + (n >> 2);
            float v = 0.0f;
            if (k < INF)      v = Wih1[(size_t)R * INF + k];
            else if (k < K1)  v = Whh1[(size_t)R * HID_ + (k - INF)];
            g_B1t[r] = v;
            continue;
        }
        r -= S1;
        if (r < S2) {
            int k = (int)(r / NG), n = (int)(r % NG);
            int R = (n & 3) * HID_ + (n >> 2);
            g_B2[r] = (k < HID_) ? Wih2[(size_t)R * HID_ + k]
                                 : Whh2[(size_t)R * HID_ + (k - HID_)];
            continue;
        }
        r -= S2;
        if (r < S2) {
            int k = (int)(r / NG), n = (int)(r % NG);
            int R = (n & 3) * HID_ + (n >> 2);
            g_B3[r] = (k < HID_) ? Wih3[(size_t)R * HID_ + k]
                                 : Whh3[(size_t)R * HID_ + (k - HID_)];
            continue;
        }
        r -= S2;
        if (r < S4) {
            int k = (int)(r / INF), o = (int)(r % INF);
            g_Bd[r] = Wd[(size_t)o * HID_ + k];
            continue;
        }
        r -= S4;
        {
            int L = (int)(r / NG), n = (int)(r % NG);
            int R = (n & 3) * HID_ + (n >> 2);
            float v = (L == 0) ? bih1[R] + bhh1[R]
                    : (L == 1) ? bih2[R] + bhh2[R]
                               : bih3[R] + bhh3[R];
            g_bias[L][n] = v;
        }
    }
}

// ---------------- per-step fused gates GEMM + LSTM pointwise ----------------
// Grid: (32 N-tiles, 2 M-tiles, 3 layers). Block 256 thr, 128x128x8 tiling, TM=TN=8.
__global__ __launch_bounds__(256, 2)
void gates_kernel(const float* __restrict__ rs, int t, int teacher) {
    const int z  = blockIdx.z;
    const int p  = t & 1;
    const int K  = (z == 0) ? K1  : K2;
    const int Kp = (z == 0) ? K1P : K2;
    const float* __restrict__ Bm   = (z == 0) ? g_B1t : (z == 1) ? g_B2 : g_B3;
    const float* __restrict__ bias = g_bias[z];

    const float* h_old0 = g_h[p][0];
    const float* h_old1 = g_h[p][1];
    const float* h_old2 = (t == 0) ? g_zero : (g_hist + (size_t)(t - 1) * SL);

    // A = [ srcA0 (L0 cols, stride sA0) | srcA1 (K-L0 cols, stride HID_) ]
    const float* srcA0; const float* srcA1; int L0; int sA0;
    if (z == 0) {
        L0 = INF;
        srcA0 = teacher ? (rs + (size_t)t * INF) : g_prev;
        sA0   = teacher ? (T_ * INF) : INF;
        srcA1 = h_old0;
    } else if (z == 1) {
        L0 = HID_; srcA0 = h_old0; sA0 = HID_; srcA1 = h_old1;
    } else {
        L0 = HID_; srcA0 = h_old1; sA0 = HID_; srcA1 = h_old2;
    }

    __shared__ __align__(16) float As[8][128];
    __shared__ __align__(16) float Bs[8][128];

    const int tid    = threadIdx.x;
    const int m_base = blockIdx.y * 128;
    const int n_base = blockIdx.x * 128;
    const int am  = tid >> 1;           // A row within tile (0..127)
    const int ak0 = (tid & 1) << 2;     // A k-offset (0 or 4)
    const int bkk = tid >> 5;           // B k row (0..7)
    const int bnn = (tid & 31) << 2;    // B n (0..124)
    const int trow = (tid >> 4) << 3;
    const int tcol = (tid & 15) << 3;
    const int bglob = m_base + am;      // global batch row for A loads

    float acc[8][8];
#pragma unroll
    for (int r = 0; r < 8; r++)
#pragma unroll
        for (int c = 0; c < 8; c++) acc[r][c] = 0.0f;

    for (int k0 = 0; k0 < Kp; k0 += 8) {
#pragma unroll
        for (int i = 0; i < 4; i++) {
            int k = k0 + ak0 + i;
            float v;
            if (k < L0)     v = srcA0[(size_t)bglob * sA0 + k];
            else if (k < K) v = srcA1[(size_t)bglob * HID_ + (k - L0)];
            else            v = 0.0f;
            As[ak0 + i][am] = v;
        }
        float4 bv = *reinterpret_cast<const float4*>(&Bm[(size_t)(k0 + bkk) * NG + n_base + bnn]);
        *reinterpret_cast<float4*>(&Bs[bkk][bnn]) = bv;
        __syncthreads();
#pragma unroll
        for (int kk = 0; kk < 8; kk++) {
            float a[8], bb[8];
            *reinterpret_cast<float4*>(a)      = *reinterpret_cast<const float4*>(&As[kk][trow]);
            *reinterpret_cast<float4*>(a + 4)  = *reinterpret_cast<const float4*>(&As[kk][trow + 4]);
            *reinterpret_cast<float4*>(bb)     = *reinterpret_cast<const float4*>(&Bs[kk][tcol]);
            *reinterpret_cast<float4*>(bb + 4) = *reinterpret_cast<const float4*>(&Bs[kk][tcol + 4]);
#pragma unroll
            for (int r = 0; r < 8; r++)
#pragma unroll
                for (int c = 0; c < 8; c++)
                    acc[r][c] = fmaf(a[r], bb[c], acc[r][c]);
        }
        __syncthreads();
    }

    // Fused LSTM pointwise: cols are (i,f,g,o) quads thanks to row reordering.
    float* cbuf  = g_c[z];
    float* hnew  = g_h[p ^ 1][z];
    float* histw = g_hist + (size_t)t * SL;
#pragma unroll
    for (int r = 0; r < 8; r++) {
        int b = m_base + trow + r;
#pragma unroll
        for (int q = 0; q < 2; q++) {
            int n0 = n_base + tcol + q * 4;
            float iv = acc[r][q * 4 + 0] + bias[n0 + 0];
            float fv = acc[r][q * 4 + 1] + bias[n0 + 1];
            float gv = acc[r][q * 4 + 2] + bias[n0 + 2];
            float ov = acc[r][q * 4 + 3] + bias[n0 + 3];
            int j = n0 >> 2;
            size_t off = (size_t)b * HID_ + j;
            float cold = cbuf[off];
            float cn = sigmoidf_(fv) * cold + sigmoidf_(iv) * tanhf(gv);
            float hn = sigmoidf_(ov) * tanhf(cn);
            cbuf[off] = cn;
            if (z == 2) histw[off] = hn;   // layer3 h lives in history
            else        hnew[off]  = hn;
        }
    }
}

// ---------------- feedback dense: prev_out = h2_t @ Wd^T + bd (only before free-run steps)
__global__ __launch_bounds__(256)
void feedback_kernel(int t, const float* __restrict__ bd) {
    const float* __restrict__ A = g_hist + (size_t)t * SL;   // [256][1024]
    __shared__ float As[8][64];
    __shared__ float Bs[8][64];
    const int tid = threadIdx.x;
    const int m_base = blockIdx.y * 64;
    const int n_base = blockIdx.x * 64;
    const int am = tid >> 2;          // 0..63
    const int ak = (tid & 3) << 1;    // 0,2,4,6
    const int bn = (tid & 31) << 1;
    const int bkk = tid >> 5;
    const int trow = (tid >> 4) << 2, tcol = (tid & 15) << 2;

    float acc[4][4];
#pragma unroll
    for (int r = 0; r < 4; r++)
#pragma unroll
        for (int c = 0; c < 4; c++) acc[r][c] = 0.0f;

    for (int k0 = 0; k0 < HID_; k0 += 8) {
#pragma unroll
        for (int i = 0; i < 2; i++)
            As[ak + i][am] = A[(size_t)(m_base + am) * HID_ + k0 + ak + i];
#pragma unroll
        for (int i = 0; i < 2; i++) {
            int n = n_base + bn + i;
            Bs[bkk][bn + i] = (n < INF) ? g_Bd[(size_t)(k0 + bkk) * INF + n] : 0.0f;
        }
        __syncthreads();
#pragma unroll
        for (int kk = 0; kk < 8; kk++) {
            float a[4], bb[4];
#pragma unroll
            for (int i = 0; i < 4; i++) { a[i] = As[kk][trow + i]; bb[i] = Bs[kk][tcol + i]; }
#pragma unroll
            for (int r = 0; r < 4; r++)
#pragma unroll
                for (int c = 0; c < 4; c++)
                    acc[r][c] = fmaf(a[r], bb[c], acc[r][c]);
        }
        __syncthreads();
    }
#pragma unroll
    for (int r = 0; r < 4; r++)
#pragma unroll
        for (int c = 0; c < 4; c++) {
            int n = n_base + tcol + c;
            if (n < INF)
                g_prev[(size_t)(m_base + trow + r) * INF + n] = acc[r][c] + bd[n];
        }
}

// ---------------- final batched dense: Out[t,b,:] = hist[t,b,:] @ Wd^T + bd ----------------
__global__ __launch_bounds__(256, 2)
void dense_kernel(float* __restrict__ out, const float* __restrict__ bd) {
    __shared__ __align__(16) float As[8][128];
    __shared__ __align__(16) float Bs[8][128];
    const int tid = threadIdx.x;
    const int m_base = blockIdx.y * 128;   // rows = t*256 + b, total 25600
    const int n_base = blockIdx.x * 128;
    const int am = tid >> 1, ak0 = (tid & 1) << 2;
    const int bkk = tid >> 5, bnn = (tid & 31) << 2;
    const int trow = (tid >> 4) << 3, tcol = (tid & 15) << 3;
    const int ridx = m_base + am;

    float acc[8][8];
#pragma unroll
    for (int r = 0; r < 8; r++)
#pragma unroll
        for (int c = 0; c < 8; c++) acc[r][c] = 0.0f;

    for (int k0 = 0; k0 < HID_; k0 += 8) {
#pragma unroll
        for (int i = 0; i < 4; i++)
            As[ak0 + i][am] = g_hist[(size_t)ridx * HID_ + k0 + ak0 + i];
#pragma unroll
        for (int i = 0; i < 4; i++) {
            int n = n_base + bnn + i;
            Bs[bkk][bnn + i] = (n < INF) ? g_Bd[(size_t)(k0 + bkk) * INF + n] : 0.0f;
        }
        __syncthreads();
#pragma unroll
        for (int kk = 0; kk < 8; kk++) {
            float a[8], bb[8];
            *reinterpret_cast<float4*>(a)      = *reinterpret_cast<const float4*>(&As[kk][trow]);
            *reinterpret_cast<float4*>(a + 4)  = *reinterpret_cast<const float4*>(&As[kk][trow + 4]);
            *reinterpret_cast<float4*>(bb)     = *reinterpret_cast<const float4*>(&Bs[kk][tcol]);
            *reinterpret_cast<float4*>(bb + 4) = *reinterpret_cast<const float4*>(&Bs[kk][tcol + 4]);
#pragma unroll
            for (int r = 0; r < 8; r++)
#pragma unroll
                for (int c = 0; c < 8; c++)
                    acc[r][c] = fmaf(a[r], bb[c], acc[r][c]);
        }
        __syncthreads();
    }
#pragma unroll
    for (int r = 0; r < 8; r++) {
        int row = m_base + trow + r;
        int tt = row >> 8, bb = row & 255;
#pragma unroll
        for (int c = 0; c < 8; c++) {
            int n = n_base + tcol + c;
            if (n < INF)
                out[(size_t)bb * (T_ * INF) + (size_t)tt * INF + n] = acc[r][c] + bd[n];
        }
    }
}

// ---------------- launch ----------------
extern "C" void kernel_launch(void* const* d_in, const int* in_sizes, int n_in,
                              void* d_out, int out_size) {
    (void)in_sizes; (void)n_in; (void)out_size;
    const float* rs   = (const float*)d_in[0];
    const float* Wih1 = (const float*)d_in[1];
    const float* Whh1 = (const float*)d_in[2];
    const float* bih1 = (const float*)d_in[3];
    const float* bhh1 = (const float*)d_in[4];
    const float* Wih2 = (const float*)d_in[5];
    const float* Whh2 = (const float*)d_in[6];
    const float* bih2 = (const float*)d_in[7];
    const float* bhh2 = (const float*)d_in[8];
    const float* Wih3 = (const float*)d_in[9];
    const float* Whh3 = (const float*)d_in[10];
    const float* bih3 = (const float*)d_in[11];
    const float* bhh3 = (const float*)d_in[12];
    const float* Wd   = (const float*)d_in[13];
    const float* bd   = (const float*)d_in[14];
    float* out = (float*)d_out;

    k_zero<<<1024, 256>>>();
    k_setup<<<4096, 256>>>(Wih1, Whh1, Wih2, Whh2, Wih3, Whh3,
                           bih1, bhh1, bih2, bhh2, bih3, bhh3, Wd);

    for (int t = 0; t < T_; t++) {
        int teach = ((t % 10) < 5) ? 1 : 0;
        gates_kernel<<<dim3(32, 2, 3), 256>>>(rs, t, teach);
        // produce prev_out only when the NEXT step runs free (teacher-forcing off)
        if (t < T_ - 1 && ((t + 1) % 10) >= 5)
            feedback_kernel<<<dim3(4, 4), 256>>>(t, bd);
    }
    dense_kernel<<<dim3(2, 200), 256>>>(out, bd);
}

// round 6
// speedup vs baseline: 2.8567x; 2.8567x over previous
#include <cuda_runtime.h>
#include <cuda_bf16.h>
#include <math.h>
#include <stdint.h>

// ---------------- problem constants ----------------
#define B_    256
#define T_    100
#define INF   227
#define HID_  1024
#define NG    4096          // 4*HID
#define KP1   1280          // 227+1024 padded to 64
#define KP2   2048
#define SL    (B_*HID_)

#define W1SZ  (NG*KP1)
#define W2SZ  (NG*KP2)
#define WTOT  (W1SZ + 2*W2SZ)
#define A1SZ  (B_*KP1)
#define A2SZ  (B_*KP2)
#define APAR  (A1SZ + 2*A2SZ)

// SMEM tile geometry: 128 rows x 32 bf16, pitch 80B (conflict-free ldmatrix)
#define PITCH   80
#define TILEB   (128*PITCH)      // 10240 bytes per tile
#define STAGEB  (4*TILEB)        // Ah,Al,Bh,Bl = 40960
#define DSMEM   (2*STAGEB)       // double buffered = 81920

// ---------------- static device scratch ----------------
__device__ __align__(16) __nv_bfloat16 g_Wh[WTOT];     // weights hi, [n][k]
__device__ __align__(16) __nv_bfloat16 g_Wl[WTOT];     // weights lo
__device__ __align__(16) __nv_bfloat16 g_Ah[2*APAR];   // activations hi (ping-pong)
__device__ __align__(16) __nv_bfloat16 g_Al[2*APAR];   // activations lo
__device__ __align__(16) float g_bias[3*NG];           // bih+bhh, ifgo quads
__device__ __align__(16) float g_Bd[HID_*INF];         // Wd^T [k][o]
__device__ __align__(16) float g_c[3*SL];              // cell states fp32
__device__ __align__(16) float g_hist[(size_t)T_*SL];  // h2 history fp32

__device__ __forceinline__ float sigf_(float x) { return 1.0f / (1.0f + expf(-x)); }

// ---------------- PTX helpers (plain sm_80+ features only) ----------------
__device__ __forceinline__ uint32_t smem_u32(const void* p) {
    uint32_t a;
    asm("{ .reg .u64 t; cvta.to.shared.u64 t, %1; cvt.u32.u64 %0, t; }" : "=r"(a) : "l"(p));
    return a;
}
__device__ __forceinline__ void cp16(uint32_t d, const void* g) {
    asm volatile("cp.async.cg.shared.global [%0], [%1], 16;" :: "r"(d), "l"(g) : "memory");
}
__device__ __forceinline__ void cp_commit() {
    asm volatile("cp.async.commit_group;" ::: "memory");
}
__device__ __forceinline__ void ldm_x4(uint32_t* r, uint32_t a) {
    asm volatile("ldmatrix.sync.aligned.m8n8.x4.shared.b16 {%0,%1,%2,%3}, [%4];"
                 : "=r"(r[0]), "=r"(r[1]), "=r"(r[2]), "=r"(r[3]) : "r"(a));
}
__device__ __forceinline__ void mma16816(float* c, const uint32_t* a, uint32_t b0, uint32_t b1) {
    asm volatile("mma.sync.aligned.m16n8k16.row.col.f32.bf16.bf16.f32 "
                 "{%0,%1,%2,%3}, {%4,%5,%6,%7}, {%8,%9}, {%0,%1,%2,%3};"
                 : "+f"(c[0]), "+f"(c[1]), "+f"(c[2]), "+f"(c[3])
                 : "r"(a[0]), "r"(a[1]), "r"(a[2]), "r"(a[3]), "r"(b0), "r"(b1));
}

// ---------------- zero mutable state each replay ----------------
__global__ void k_zero() {
    const size_t CW = (size_t)3 * SL;
    const size_t AW = (size_t)APAR;
    const size_t N  = CW + 2 * AW;
    for (size_t i = (size_t)blockIdx.x * blockDim.x + threadIdx.x; i < N;
         i += (size_t)gridDim.x * blockDim.x) {
        if (i < CW)            g_c[i] = 0.0f;
        else if (i < CW + AW)  ((uint32_t*)g_Ah)[i - CW] = 0u;
        else                   ((uint32_t*)g_Al)[i - CW - AW] = 0u;
    }
}

// ---------------- weight reorder + bf16 split ----------------
__global__ void k_setup(const float* __restrict__ Wih1, const float* __restrict__ Whh1,
                        const float* __restrict__ Wih2, const float* __restrict__ Whh2,
                        const float* __restrict__ Wih3, const float* __restrict__ Whh3,
                        const float* __restrict__ bih1, const float* __restrict__ bhh1,
                        const float* __restrict__ bih2, const float* __restrict__ bhh2,
                        const float* __restrict__ bih3, const float* __restrict__ bhh3,
                        const float* __restrict__ Wd) {
    const long TOT = (long)WTOT + 3L * NG + (long)HID_ * INF;
    for (long idx = (long)blockIdx.x * blockDim.x + threadIdx.x; idx < TOT;
         idx += (long)gridDim.x * blockDim.x) {
        long r = idx;
        if (r < (long)WTOT) {
            int z, n, k;
            if (r < W1SZ)              { z = 0; n = (int)(r / KP1); k = (int)(r % KP1); }
            else if (r < W1SZ + W2SZ)  { long q = r - W1SZ; z = 1; n = (int)(q / KP2); k = (int)(q % KP2); }
            else                       { long q = r - W1SZ - W2SZ; z = 2; n = (int)(q / KP2); k = (int)(q % KP2); }
            int R = (n & 3) * HID_ + (n >> 2);   // ifgo-quad reorder
            float w = 0.0f;
            if (z == 0) {
                if (k < INF)       w = Wih1[(size_t)R * INF + k];
                else if (k < 1251) w = Whh1[(size_t)R * HID_ + (k - INF)];
            } else if (z == 1) {
                w = (k < HID_) ? Wih2[(size_t)R * HID_ + k] : Whh2[(size_t)R * HID_ + (k - HID_)];
            } else {
                w = (k < HID_) ? Wih3[(size_t)R * HID_ + k] : Whh3[(size_t)R * HID_ + (k - HID_)];
            }
            __nv_bfloat16 hi = __float2bfloat16(w);
            __nv_bfloat16 lo = __float2bfloat16(w - __bfloat162float(hi));
            g_Wh[r] = hi; g_Wl[r] = lo;
            continue;
        }
        r -= WTOT;
        if (r < 3L * NG) {
            int L = (int)(r / NG), n = (int)(r % NG);
            int R = (n & 3) * HID_ + (n >> 2);
            float v = (L == 0) ? bih1[R] + bhh1[R]
                    : (L == 1) ? bih2[R] + bhh2[R]
                               : bih3[R] + bhh3[R];
            g_bias[r] = v;
            continue;
        }
        r -= 3L * NG;
        {
            int k = (int)(r / INF), o = (int)(r % INF);
            g_Bd[r] = Wd[(size_t)o * HID_ + k];
        }
    }
}

// ---------------- teacher-forcing x split into layer1 A ----------------
__global__ void split_x(const float* __restrict__ rs, int t) {
    int i = blockIdx.x * blockDim.x + threadIdx.x;
    if (i >= B_ * INF) return;
    int b = i / INF, n = i % INF;
    float v = rs[(size_t)b * (T_ * INF) + (size_t)t * INF + n];
    __nv_bfloat16 hi = __float2bfloat16(v);
    __nv_bfloat16 lo = __float2bfloat16(v - __bfloat162float(hi));
    size_t o = (size_t)(t & 1) * APAR + (size_t)b * KP1 + n;
    g_Ah[o] = hi; g_Al[o] = lo;
}

// ---------------- fused HMMA gates GEMM + LSTM pointwise ----------------
// grid (32 ntiles, 2 mtiles, 3 layers), 256 thr = 8 warps (2 M x 4 N),
// CTA tile 128x128, warp tile 64x32, K-chunk 32, cp.async double buffer.
// Ootomo 3-term: acc += Ah*Bh + Ah*Bl + Al*Bh (fp32 accum).
__global__ void __launch_bounds__(256, 1) gates_kernel(int t) {
    extern __shared__ char dynsmem[];
    const int tid = threadIdx.x;
    const int warp = tid >> 5, lane = tid & 31;
    const int warpm = warp >> 2, warpn = warp & 3;
    const int z = blockIdx.z;
    const int p = t & 1, pn = p ^ 1;
    const int Kp  = (z == 0) ? KP1 : KP2;
    const int nch = Kp >> 5;                      // K-chunks of 32
    const size_t aoff = (z == 0) ? 0 : (z == 1) ? (size_t)A1SZ : (size_t)(A1SZ + A2SZ);
    const size_t woff = (z == 0) ? 0 : (z == 1) ? (size_t)W1SZ : (size_t)(W1SZ + W2SZ);
    const __nv_bfloat16* __restrict__ Ahg = g_Ah + (size_t)p * APAR + aoff;
    const __nv_bfloat16* __restrict__ Alg = g_Al + (size_t)p * APAR + aoff;
    const __nv_bfloat16* __restrict__ Whg = g_Wh + woff;
    const __nv_bfloat16* __restrict__ Wlg = g_Wl + woff;
    const int mbase = blockIdx.y * 128, nbase = blockIdx.x * 128;
    const uint32_t sbase = smem_u32(dynsmem);

    // ---- async stage loader: 2048 x 16B per stage, 8 per thread ----
    auto issue = [&](int ch) {
        const uint32_t sb = sbase + (ch & 1) * STAGEB;
        const int k0 = ch << 5;
#pragma unroll
        for (int it = 0; it < 8; it++) {
            int s = it * 256 + tid;           // 0..2047
            int tile = s >> 9;                // 0:Ah 1:Al 2:Bh 3:Bl
            int r  = (s & 511) >> 2;
            int c4 = s & 3;
            uint32_t d = sb + tile * TILEB + r * PITCH + c4 * 16;
            const __nv_bfloat16* gp;
            if (tile == 0)      gp = Ahg + (size_t)(mbase + r) * Kp + k0 + c4 * 8;
            else if (tile == 1) gp = Alg + (size_t)(mbase + r) * Kp + k0 + c4 * 8;
            else if (tile == 2) gp = Whg + (size_t)(nbase + r) * Kp + k0 + c4 * 8;
            else                gp = Wlg + (size_t)(nbase + r) * Kp + k0 + c4 * 8;
            cp16(d, gp);
        }
        cp_commit();
    };

    float acc[4][4][4];
#pragma unroll
    for (int mf = 0; mf < 4; mf++)
#pragma unroll
        for (int nf = 0; nf < 4; nf++)
#pragma unroll
            for (int i = 0; i < 4; i++) acc[mf][nf][i] = 0.0f;

    issue(0);
    for (int ch = 0; ch < nch; ch++) {
        if (ch + 1 < nch) {
            issue(ch + 1);
            asm volatile("cp.async.wait_group 1;" ::: "memory");
        } else {
            asm volatile("cp.async.wait_group 0;" ::: "memory");
        }
        __syncthreads();
        const uint32_t sb = sbase + (ch & 1) * STAGEB;
#pragma unroll
        for (int kk = 0; kk < 2; kk++) {
            uint32_t ah[4][4], al[4][4];
#pragma unroll
            for (int mf = 0; mf < 4; mf++) {
                uint32_t addr = sb + (uint32_t)(warpm * 64 + mf * 16 + (lane & 15)) * PITCH
                              + kk * 32 + (lane >> 4) * 16;
                ldm_x4(ah[mf], addr);
                ldm_x4(al[mf], addr + TILEB);
            }
            uint32_t bh[2][4], bl[2][4];
#pragma unroll
            for (int nf2 = 0; nf2 < 2; nf2++) {
                int nrow = warpn * 32 + nf2 * 16 + (lane & 7) + ((lane >> 4) << 3);
                uint32_t addr = sb + 2 * TILEB + (uint32_t)nrow * PITCH
                              + kk * 32 + ((lane >> 3) & 1) * 16;
                ldm_x4(bh[nf2], addr);
                ldm_x4(bl[nf2], addr + TILEB);
            }
#pragma unroll
            for (int mf = 0; mf < 4; mf++)
#pragma unroll
                for (int nf = 0; nf < 4; nf++) {
                    const int nf2 = nf >> 1, h = nf & 1;
                    uint32_t b0h = bh[nf2][h * 2], b1h = bh[nf2][h * 2 + 1];
                    uint32_t b0l = bl[nf2][h * 2], b1l = bl[nf2][h * 2 + 1];
                    mma16816(acc[mf][nf], ah[mf], b0h, b1h);
                    mma16816(acc[mf][nf], ah[mf], b0l, b1l);
                    mma16816(acc[mf][nf], al[mf], b0h, b1h);
                }
        }
        __syncthreads();
    }

    // ---- epilogue: shuffle c-frags into (i,f,g,o) quads, LSTM pointwise ----
    // c-frag layout: c0,c1 = row lane/4, cols 2c,2c+1; c2,c3 = row+8.
    const int c    = lane & 3;
    const int pairq = c >> 1;   // which quad (cols 0-3 vs 4-7) within 8-col frag
    const int pos  = c & 1;     // 0: handle row rbase; 1: handle row rbase+8
    const int rbase = lane >> 2;

    float4 bias4[4];
#pragma unroll
    for (int nf = 0; nf < 4; nf++) {
        int n0 = nbase + warpn * 32 + nf * 8 + pairq * 4;
        bias4[nf] = *(const float4*)(g_bias + z * NG + n0);
    }

    float* cpz = g_c + (size_t)z * SL;
    size_t hb0, hb1 = 0; int st0;
    if (z == 0)      { hb0 = (size_t)pn * APAR + 227;                st0 = KP1;
                       hb1 = (size_t)pn * APAR + A1SZ; }
    else if (z == 1) { hb0 = (size_t)pn * APAR + A1SZ + 1024;        st0 = KP2;
                       hb1 = (size_t)pn * APAR + A1SZ + A2SZ; }
    else             { hb0 = (size_t)pn * APAR + A1SZ + A2SZ + 1024; st0 = KP2; }

#pragma unroll
    for (int mf = 0; mf < 4; mf++) {
#pragma unroll
        for (int nf = 0; nf < 4; nf++) {
            float a0 = acc[mf][nf][0], a1 = acc[mf][nf][1];
            float a2 = acc[mf][nf][2], a3 = acc[mf][nf][3];
            float p0 = __shfl_xor_sync(0xffffffffu, a0, 1);
            float p1 = __shfl_xor_sync(0xffffffffu, a1, 1);
            float p2 = __shfl_xor_sync(0xffffffffu, a2, 1);
            float p3 = __shfl_xor_sync(0xffffffffu, a3, 1);
            float iv, fv, gv, ov; int row;
            if (pos == 0) { iv = a0; fv = a1; gv = p0; ov = p1; row = rbase; }
            else          { iv = p2; fv = p3; gv = a2; ov = a3; row = rbase + 8; }
            iv += bias4[nf].x; fv += bias4[nf].y; gv += bias4[nf].z; ov += bias4[nf].w;

            int b  = mbase + warpm * 64 + mf * 16 + row;
            int n0 = nbase + warpn * 32 + nf * 8 + pairq * 4;
            int j  = n0 >> 2;
            size_t co = (size_t)b * HID_ + j;
            float cold = cpz[co];
            float cn = sigf_(fv) * cold + sigf_(iv) * tanhf(gv);
            float hn = sigf_(ov) * tanhf(cn);
            cpz[co] = cn;
            __nv_bfloat16 hi = __float2bfloat16(hn);
            __nv_bfloat16 lo = __float2bfloat16(hn - __bfloat162float(hi));
            size_t o0 = hb0 + (size_t)b * st0 + j;
            g_Ah[o0] = hi; g_Al[o0] = lo;
            if (z < 2) {
                size_t o1 = hb1 + (size_t)b * KP2 + j;
                g_Ah[o1] = hi; g_Al[o1] = lo;
            } else {
                g_hist[((size_t)t * B_ + b) * HID_ + j] = hn;
            }
        }
    }
}

// ---------------- feedback: x_{t+1} = h2[t] @ Wd^T + bd (free-run input) ----
// 64 blocks x 4 batch rows, thread = output feature.
__global__ __launch_bounds__(256) void feedback_kernel(int t, const float* __restrict__ bd) {
    __shared__ float sh[4][HID_];
    const int tid = threadIdx.x, bg = blockIdx.x;
    for (int i = tid; i < 4 * HID_; i += 256)
        sh[i >> 10][i & 1023] = g_hist[((size_t)t * B_ + bg * 4 + (i >> 10)) * HID_ + (i & 1023)];
    __syncthreads();
    const int n = tid;
    if (n >= INF) return;
    float acc[4] = {0, 0, 0, 0};
    for (int k = 0; k < HID_; k += 4) {
#pragma unroll
        for (int kk = 0; kk < 4; kk++) {
            float w = g_Bd[(size_t)(k + kk) * INF + n];
#pragma unroll
            for (int r = 0; r < 4; r++) acc[r] = fmaf(sh[r][k + kk], w, acc[r]);
        }
    }
    const int pnx = (t + 1) & 1;
#pragma unroll
    for (int r = 0; r < 4; r++) {
        float v = acc[r] + bd[n];
        __nv_bfloat16 hi = __float2bfloat16(v);
        __nv_bfloat16 lo = __float2bfloat16(v - __bfloat162float(hi));
        size_t o = (size_t)pnx * APAR + (size_t)(bg * 4 + r) * KP1 + n;
        g_Ah[o] = hi; g_Al[o] = lo;
    }
}

// ---------------- final batched dense: Out[t,b,:] = hist[t,b,:] @ Wd^T + bd ----
__global__ __launch_bounds__(256, 2)
void dense_kernel(float* __restrict__ out, const float* __restrict__ bd) {
    __shared__ __align__(16) float As[8][128];
    __shared__ __align__(16) float Bs[8][128];
    const int tid = threadIdx.x;
    const int m_base = blockIdx.y * 128;
    const int n_base = blockIdx.x * 128;
    const int am = tid >> 1, ak0 = (tid & 1) << 2;
    const int bkk = tid >> 5, bnn = (tid & 31) << 2;
    const int trow = (tid >> 4) << 3, tcol = (tid & 15) << 3;
    const int ridx = m_base + am;

    float acc[8][8];
#pragma unroll
    for (int r = 0; r < 8; r++)
#pragma unroll
        for (int cc = 0; cc < 8; cc++) acc[r][cc] = 0.0f;

    for (int k0 = 0; k0 < HID_; k0 += 8) {
#pragma unroll
        for (int i = 0; i < 4; i++)
            As[ak0 + i][am] = g_hist[(size_t)ridx * HID_ + k0 + ak0 + i];
#pragma unroll
        for (int i = 0; i < 4; i++) {
            int n = n_base + bnn + i;
            Bs[bkk][bnn + i] = (n < INF) ? g_Bd[(size_t)(k0 + bkk) * INF + n] : 0.0f;
        }
        __syncthreads();
#pragma unroll
        for (int kk = 0; kk < 8; kk++) {
            float a[8], bb[8];
            *reinterpret_cast<float4*>(a)      = *reinterpret_cast<const float4*>(&As[kk][trow]);
            *reinterpret_cast<float4*>(a + 4)  = *reinterpret_cast<const float4*>(&As[kk][trow + 4]);
            *reinterpret_cast<float4*>(bb)     = *reinterpret_cast<const float4*>(&Bs[kk][tcol]);
            *reinterpret_cast<float4*>(bb + 4) = *reinterpret_cast<const float4*>(&Bs[kk][tcol + 4]);
#pragma unroll
            for (int r = 0; r < 8; r++)
#pragma unroll
                for (int cc = 0; cc < 8; cc++)
                    acc[r][cc] = fmaf(a[r], bb[cc], acc[r][cc]);
        }
        __syncthreads();
    }
#pragma unroll
    for (int r = 0; r < 8; r++) {
        int row = m_base + trow + r;
        int tt = row >> 8, bb = row & 255;
#pragma unroll
        for (int cc = 0; cc < 8; cc++) {
            int n = n_base + tcol + cc;
            if (n < INF)
                out[(size_t)bb * (T_ * INF) + (size_t)tt * INF + n] = acc[r][cc] + bd[n];
        }
    }
}

// ---------------- launch ----------------
extern "C" void kernel_launch(void* const* d_in, const int* in_sizes, int n_in,
                              void* d_out, int out_size) {
    (void)in_sizes; (void)n_in; (void)out_size;
    const float* rs   = (const float*)d_in[0];
    const float* Wih1 = (const float*)d_in[1];
    const float* Whh1 = (const float*)d_in[2];
    const float* bih1 = (const float*)d_in[3];
    const float* bhh1 = (const float*)d_in[4];
    const float* Wih2 = (const float*)d_in[5];
    const float* Whh2 = (const float*)d_in[6];
    const float* bih2 = (const float*)d_in[7];
    const float* bhh2 = (const float*)d_in[8];
    const float* Wih3 = (const float*)d_in[9];
    const float* Whh3 = (const float*)d_in[10];
    const float* bih3 = (const float*)d_in[11];
    const float* bhh3 = (const float*)d_in[12];
    const float* Wd   = (const float*)d_in[13];
    const float* bd   = (const float*)d_in[14];
    float* out = (float*)d_out;

    cudaFuncSetAttribute(gates_kernel, cudaFuncAttributeMaxDynamicSharedMemorySize, DSMEM);

    k_zero<<<2048, 256>>>();
    k_setup<<<4096, 256>>>(Wih1, Whh1, Wih2, Whh2, Wih3, Whh3,
                           bih1, bhh1, bih2, bhh2, bih3, bhh3, Wd);

    for (int t = 0; t < T_; t++) {
        if ((t % 10) < 5)
            split_x<<<(B_ * INF + 255) / 256, 256>>>(rs, t);   // teacher forcing
        gates_kernel<<<dim3(32, 2, 3), 256, DSMEM>>>(t);
        if (t < T_ - 1 && ((t + 1) % 10) >= 5)
            feedback_kernel<<<64, 256>>>(t, bd);               // free-run input
    }
    dense_kernel<<<dim3(2, 200), 256>>>(out, bd);
}

// round 7
// speedup vs baseline: 2.8672x; 1.0037x over previous
#include <cuda_runtime.h>
#include <cuda_bf16.h>
#include <math.h>
#include <stdint.h>

// ---------------- problem constants ----------------
#define B_    256
#define T_    100
#define INF   227
#define HID_  1024
#define NG    4096          // 4*HID
#define KP1   1280          // 227+1024 padded to 64
#define KP2   2048
#define SL    (B_*HID_)

#define W1SZ  (NG*KP1)
#define W2SZ  (NG*KP2)
#define WTOT  (W1SZ + 2*W2SZ)
#define A1SZ  (B_*KP1)
#define A2SZ  (B_*KP2)
#define APAR  (A1SZ + 2*A2SZ)

// SMEM tile geometry: 128 rows x 32 bf16, pitch 80B (conflict-free ldmatrix)
#define PITCH   80
#define TILEB   (128*PITCH)      // 10240 bytes per tile
#define STAGEB  (4*TILEB)        // Ah,Al,Bh,Bl = 40960
#define NSTAGE  4
#define DSMEM   (NSTAGE*STAGEB)  // 163840 bytes

// ---------------- static device scratch ----------------
__device__ __align__(16) __nv_bfloat16 g_Wh[WTOT];     // weights hi, [n][k]
__device__ __align__(16) __nv_bfloat16 g_Wl[WTOT];     // weights lo
__device__ __align__(16) __nv_bfloat16 g_Ah[2*APAR];   // activations hi (ping-pong)
__device__ __align__(16) __nv_bfloat16 g_Al[2*APAR];   // activations lo
__device__ __align__(16) float g_bias[3*NG];           // bih+bhh, ifgo quads
__device__ __align__(16) float g_Bd[HID_*INF];         // Wd^T [k][o]
__device__ __align__(16) float g_c[3*SL];              // cell states fp32
__device__ __align__(16) float g_hist[(size_t)T_*SL];  // h2 history fp32

__device__ __forceinline__ float sigf_(float x) { return 1.0f / (1.0f + expf(-x)); }

// ---------------- PTX helpers (plain sm_80+ features only) ----------------
__device__ __forceinline__ uint32_t smem_u32(const void* p) {
    uint32_t a;
    asm("{ .reg .u64 t; cvta.to.shared.u64 t, %1; cvt.u32.u64 %0, t; }" : "=r"(a) : "l"(p));
    return a;
}
__device__ __forceinline__ void cp16(uint32_t d, const void* g) {
    asm volatile("cp.async.cg.shared.global [%0], [%1], 16;" :: "r"(d), "l"(g) : "memory");
}
__device__ __forceinline__ void cp_commit() {
    asm volatile("cp.async.commit_group;" ::: "memory");
}
__device__ __forceinline__ void ldm_x4(uint32_t* r, uint32_t a) {
    asm volatile("ldmatrix.sync.aligned.m8n8.x4.shared.b16 {%0,%1,%2,%3}, [%4];"
                 : "=r"(r[0]), "=r"(r[1]), "=r"(r[2]), "=r"(r[3]) : "r"(a));
}
__device__ __forceinline__ void mma16816(float* c, const uint32_t* a, uint32_t b0, uint32_t b1) {
    asm volatile("mma.sync.aligned.m16n8k16.row.col.f32.bf16.bf16.f32 "
                 "{%0,%1,%2,%3}, {%4,%5,%6,%7}, {%8,%9}, {%0,%1,%2,%3};"
                 : "+f"(c[0]), "+f"(c[1]), "+f"(c[2]), "+f"(c[3])
                 : "r"(a[0]), "r"(a[1]), "r"(a[2]), "r"(a[3]), "r"(b0), "r"(b1));
}

// ---------------- zero mutable state each replay ----------------
__global__ void k_zero() {
    const size_t CW = (size_t)3 * SL;
    const size_t AW = (size_t)APAR;
    const size_t N  = CW + 2 * AW;
    for (size_t i = (size_t)blockIdx.x * blockDim.x + threadIdx.x; i < N;
         i += (size_t)gridDim.x * blockDim.x) {
        if (i < CW)            g_c[i] = 0.0f;
        else if (i < CW + AW)  ((uint32_t*)g_Ah)[i - CW] = 0u;
        else                   ((uint32_t*)g_Al)[i - CW - AW] = 0u;
    }
}

// ---------------- weight reorder + bf16 split ----------------
__global__ void k_setup(const float* __restrict__ Wih1, const float* __restrict__ Whh1,
                        const float* __restrict__ Wih2, const float* __restrict__ Whh2,
                        const float* __restrict__ Wih3, const float* __restrict__ Whh3,
                        const float* __restrict__ bih1, const float* __restrict__ bhh1,
                        const float* __restrict__ bih2, const float* __restrict__ bhh2,
                        const float* __restrict__ bih3, const float* __restrict__ bhh3,
                        const float* __restrict__ Wd) {
    const long TOT = (long)WTOT + 3L * NG + (long)HID_ * INF;
    for (long idx = (long)blockIdx.x * blockDim.x + threadIdx.x; idx < TOT;
         idx += (long)gridDim.x * blockDim.x) {
        long r = idx;
        if (r < (long)WTOT) {
            int z, n, k;
            if (r < W1SZ)              { z = 0; n = (int)(r / KP1); k = (int)(r % KP1); }
            else if (r < W1SZ + W2SZ)  { long q = r - W1SZ; z = 1; n = (int)(q / KP2); k = (int)(q % KP2); }
            else                       { long q = r - W1SZ - W2SZ; z = 2; n = (int)(q / KP2); k = (int)(q % KP2); }
            int R = (n & 3) * HID_ + (n >> 2);   // ifgo-quad reorder
            float w = 0.0f;
            if (z == 0) {
                if (k < INF)       w = Wih1[(size_t)R * INF + k];
                else if (k < 1251) w = Whh1[(size_t)R * HID_ + (k - INF)];
            } else if (z == 1) {
                w = (k < HID_) ? Wih2[(size_t)R * HID_ + k] : Whh2[(size_t)R * HID_ + (k - HID_)];
            } else {
                w = (k < HID_) ? Wih3[(size_t)R * HID_ + k] : Whh3[(size_t)R * HID_ + (k - HID_)];
            }
            __nv_bfloat16 hi = __float2bfloat16(w);
            __nv_bfloat16 lo = __float2bfloat16(w - __bfloat162float(hi));
            g_Wh[r] = hi; g_Wl[r] = lo;
            continue;
        }
        r -= WTOT;
        if (r < 3L * NG) {
            int L = (int)(r / NG), n = (int)(r % NG);
            int R = (n & 3) * HID_ + (n >> 2);
            float v = (L == 0) ? bih1[R] + bhh1[R]
                    : (L == 1) ? bih2[R] + bhh2[R]
                               : bih3[R] + bhh3[R];
            g_bias[r] = v;
            continue;
        }
        r -= 3L * NG;
        {
            int k = (int)(r / INF), o = (int)(r % INF);
            g_Bd[r] = Wd[(size_t)o * INF ? 0 : 0]; // placeholder never taken
        }
    }
}

// (separate tiny kernel for g_Bd to keep k_setup branchless bug-free)
__global__ void k_setup_bd(const float* __restrict__ Wd) {
    int i = blockIdx.x * blockDim.x + threadIdx.x;
    if (i >= HID_ * INF) return;
    int k = i / INF, o = i % INF;
    g_Bd[i] = Wd[(size_t)o * HID_ + k];
}

// ---------------- teacher-forcing x split into layer1 A ----------------
__global__ void split_x(const float* __restrict__ rs, int t) {
    int i = blockIdx.x * blockDim.x + threadIdx.x;
    if (i >= B_ * INF) return;
    int b = i / INF, n = i % INF;
    float v = rs[(size_t)b * (T_ * INF) + (size_t)t * INF + n];
    __nv_bfloat16 hi = __float2bfloat16(v);
    __nv_bfloat16 lo = __float2bfloat16(v - __bfloat162float(hi));
    size_t o = (size_t)(t & 1) * APAR + (size_t)b * KP1 + n;
    g_Ah[o] = hi; g_Al[o] = lo;
}

// ---------------- fused HMMA gates GEMM + LSTM pointwise ----------------
// grid (32 ntiles, 2 mtiles, 3 layers), 512 thr = 16 warps (4 M x 4 N),
// CTA tile 128x128, warp tile 32x32, K-chunk 32, 4-stage cp.async pipeline.
// Ootomo 3-term: acc += Ah*Bh + Ah*Bl + Al*Bh (fp32 accum).
__global__ void __launch_bounds__(512, 1) gates_kernel(int t) {
    extern __shared__ char dynsmem[];
    const int tid = threadIdx.x;
    const int warp = tid >> 5, lane = tid & 31;
    const int warpm = warp >> 2, warpn = warp & 3;
    const int z = blockIdx.z;
    const int p = t & 1, pn = p ^ 1;
    const int Kp  = (z == 0) ? KP1 : KP2;
    const int nch = Kp >> 5;                      // K-chunks of 32
    const size_t aoff = (z == 0) ? 0 : (z == 1) ? (size_t)A1SZ : (size_t)(A1SZ + A2SZ);
    const size_t woff = (z == 0) ? 0 : (z == 1) ? (size_t)W1SZ : (size_t)(W1SZ + W2SZ);
    const __nv_bfloat16* __restrict__ Ahg = g_Ah + (size_t)p * APAR + aoff;
    const __nv_bfloat16* __restrict__ Alg = g_Al + (size_t)p * APAR + aoff;
    const __nv_bfloat16* __restrict__ Whg = g_Wh + woff;
    const __nv_bfloat16* __restrict__ Wlg = g_Wl + woff;
    const int mbase = blockIdx.y * 128, nbase = blockIdx.x * 128;
    const uint32_t sbase = smem_u32(dynsmem);

    // ---- async stage loader: 2048 x 16B per stage, 4 per thread; always commits
    auto issue = [&](int ch) {
        if (ch < nch) {
            const uint32_t sb = sbase + (ch & (NSTAGE - 1)) * STAGEB;
            const int k0 = ch << 5;
#pragma unroll
            for (int it = 0; it < 4; it++) {
                int s = it * 512 + tid;           // 0..2047
                int tile = s >> 9;                // 0:Ah 1:Al 2:Bh 3:Bl
                int r  = (s & 511) >> 2;
                int c4 = s & 3;
                uint32_t d = sb + tile * TILEB + r * PITCH + c4 * 16;
                const __nv_bfloat16* gp;
                if (tile == 0)      gp = Ahg + (size_t)(mbase + r) * Kp + k0 + c4 * 8;
                else if (tile == 1) gp = Alg + (size_t)(mbase + r) * Kp + k0 + c4 * 8;
                else if (tile == 2) gp = Whg + (size_t)(nbase + r) * Kp + k0 + c4 * 8;
                else                gp = Wlg + (size_t)(nbase + r) * Kp + k0 + c4 * 8;
                cp16(d, gp);
            }
        }
        cp_commit();   // empty group at tail keeps pending-count invariant
    };

    float acc[2][4][4];
#pragma unroll
    for (int mf = 0; mf < 2; mf++)
#pragma unroll
        for (int nf = 0; nf < 4; nf++)
#pragma unroll
            for (int i = 0; i < 4; i++) acc[mf][nf][i] = 0.0f;

    issue(0); issue(1); issue(2);
    for (int ch = 0; ch < nch; ch++) {
        asm volatile("cp.async.wait_group 2;" ::: "memory");
        __syncthreads();                 // stage ch ready; stage (ch-1) fully consumed
        issue(ch + 3);                   // refill buffer (ch+3)&3 == (ch-1)&3
        const uint32_t sb = sbase + (ch & (NSTAGE - 1)) * STAGEB;
#pragma unroll
        for (int kk = 0; kk < 2; kk++) {
            uint32_t ah[2][4], al[2][4];
#pragma unroll
            for (int mf = 0; mf < 2; mf++) {
                uint32_t addr = sb + (uint32_t)(warpm * 32 + mf * 16 + (lane & 15)) * PITCH
                              + kk * 32 + (lane >> 4) * 16;
                ldm_x4(ah[mf], addr);
                ldm_x4(al[mf], addr + TILEB);
            }
            uint32_t bh[2][4], bl[2][4];
#pragma unroll
            for (int nf2 = 0; nf2 < 2; nf2++) {
                int nrow = warpn * 32 + nf2 * 16 + (lane & 7) + ((lane >> 4) << 3);
                uint32_t addr = sb + 2 * TILEB + (uint32_t)nrow * PITCH
                              + kk * 32 + ((lane >> 3) & 1) * 16;
                ldm_x4(bh[nf2], addr);
                ldm_x4(bl[nf2], addr + TILEB);
            }
#pragma unroll
            for (int mf = 0; mf < 2; mf++)
#pragma unroll
                for (int nf = 0; nf < 4; nf++) {
                    const int nf2 = nf >> 1, h = nf & 1;
                    uint32_t b0h = bh[nf2][h * 2], b1h = bh[nf2][h * 2 + 1];
                    uint32_t b0l = bl[nf2][h * 2], b1l = bl[nf2][h * 2 + 1];
                    mma16816(acc[mf][nf], ah[mf], b0h, b1h);
                    mma16816(acc[mf][nf], ah[mf], b0l, b1l);
                    mma16816(acc[mf][nf], al[mf], b0h, b1h);
                }
        }
        __syncthreads();                 // all warps done with stage ch before reuse
    }

    // ---- epilogue: shuffle c-frags into (i,f,g,o) quads, LSTM pointwise ----
    const int c     = lane & 3;
    const int pairq = c >> 1;
    const int pos   = c & 1;
    const int rbase = lane >> 2;

    float4 bias4[4];
#pragma unroll
    for (int nf = 0; nf < 4; nf++) {
        int n0 = nbase + warpn * 32 + nf * 8 + pairq * 4;
        bias4[nf] = *(const float4*)(g_bias + z * NG + n0);
    }

    float* cpz = g_c + (size_t)z * SL;
    size_t hb0, hb1 = 0; int st0;
    if (z == 0)      { hb0 = (size_t)pn * APAR + 227;                st0 = KP1;
                       hb1 = (size_t)pn * APAR + A1SZ; }
    else if (z == 1) { hb0 = (size_t)pn * APAR + A1SZ + 1024;        st0 = KP2;
                       hb1 = (size_t)pn * APAR + A1SZ + A2SZ; }
    else             { hb0 = (size_t)pn * APAR + A1SZ + A2SZ + 1024; st0 = KP2; }

#pragma unroll
    for (int mf = 0; mf < 2; mf++) {
#pragma unroll
        for (int nf = 0; nf < 4; nf++) {
            float a0 = acc[mf][nf][0], a1 = acc[mf][nf][1];
            float a2 = acc[mf][nf][2], a3 = acc[mf][nf][3];
            float p0 = __shfl_xor_sync(0xffffffffu, a0, 1);
            float p1 = __shfl_xor_sync(0xffffffffu, a1, 1);
            float p2 = __shfl_xor_sync(0xffffffffu, a2, 1);
            float p3 = __shfl_xor_sync(0xffffffffu, a3, 1);
            float iv, fv, gv, ov; int row;
            if (pos == 0) { iv = a0; fv = a1; gv = p0; ov = p1; row = rbase; }
            else          { iv = p2; fv = p3; gv = a2; ov = a3; row = rbase + 8; }
            iv += bias4[nf].x; fv += bias4[nf].y; gv += bias4[nf].z; ov += bias4[nf].w;

            int b  = mbase + warpm * 32 + mf * 16 + row;
            int n0 = nbase + warpn * 32 + nf * 8 + pairq * 4;
            int j  = n0 >> 2;
            size_t co = (size_t)b * HID_ + j;
            float cold = cpz[co];
            float cn = sigf_(fv) * cold + sigf_(iv) * tanhf(gv);
            float hn = sigf_(ov) * tanhf(cn);
            cpz[co] = cn;
            __nv_bfloat16 hi = __float2bfloat16(hn);
            __nv_bfloat16 lo = __float2bfloat16(hn - __bfloat162float(hi));
            size_t o0 = hb0 + (size_t)b * st0 + j;
            g_Ah[o0] = hi; g_Al[o0] = lo;
            if (z < 2) {
                size_t o1 = hb1 + (size_t)b * KP2 + j;
                g_Ah[o1] = hi; g_Al[o1] = lo;
            } else {
                g_hist[((size_t)t * B_ + b) * HID_ + j] = hn;
            }
        }
    }
}

// ---------------- feedback: x_{t+1} = h2[t] @ Wd^T + bd (free-run input) ----
__global__ __launch_bounds__(256) void feedback_kernel(int t, const float* __restrict__ bd) {
    __shared__ float sh[4][HID_];
    const int tid = threadIdx.x, bg = blockIdx.x;
    for (int i = tid; i < 4 * HID_; i += 256)
        sh[i >> 10][i & 1023] = g_hist[((size_t)t * B_ + bg * 4 + (i >> 10)) * HID_ + (i & 1023)];
    __syncthreads();
    const int n = tid;
    if (n >= INF) return;
    float acc[4] = {0, 0, 0, 0};
    for (int k = 0; k < HID_; k += 4) {
#pragma unroll
        for (int kk = 0; kk < 4; kk++) {
            float w = g_Bd[(size_t)(k + kk) * INF + n];
#pragma unroll
            for (int r = 0; r < 4; r++) acc[r] = fmaf(sh[r][k + kk], w, acc[r]);
        }
    }
    const int pnx = (t + 1) & 1;
#pragma unroll
    for (int r = 0; r < 4; r++) {
        float v = acc[r] + bd[n];
        __nv_bfloat16 hi = __float2bfloat16(v);
        __nv_bfloat16 lo = __float2bfloat16(v - __bfloat162float(hi));
        size_t o = (size_t)pnx * APAR + (size_t)(bg * 4 + r) * KP1 + n;
        g_Ah[o] = hi; g_Al[o] = lo;
    }
}

// ---------------- final batched dense: Out[t,b,:] = hist[t,b,:] @ Wd^T + bd ----
__global__ __launch_bounds__(256, 2)
void dense_kernel(float* __restrict__ out, const float* __restrict__ bd) {
    __shared__ __align__(16) float As[8][128];
    __shared__ __align__(16) float Bs[8][128];
    const int tid = threadIdx.x;
    const int m_base = blockIdx.y * 128;
    const int n_base = blockIdx.x * 128;
    const int am = tid >> 1, ak0 = (tid & 1) << 2;
    const int bkk = tid >> 5, bnn = (tid & 31) << 2;
    const int trow = (tid >> 4) << 3, tcol = (tid & 15) << 3;
    const int ridx = m_base + am;

    float acc[8][8];
#pragma unroll
    for (int r = 0; r < 8; r++)
#pragma unroll
        for (int cc = 0; cc < 8; cc++) acc[r][cc] = 0.0f;

    for (int k0 = 0; k0 < HID_; k0 += 8) {
#pragma unroll
        for (int i = 0; i < 4; i++)
            As[ak0 + i][am] = g_hist[(size_t)ridx * HID_ + k0 + ak0 + i];
#pragma unroll
        for (int i = 0; i < 4; i++) {
            int n = n_base + bnn + i;
            Bs[bkk][bnn + i] = (n < INF) ? g_Bd[(size_t)(k0 + bkk) * INF + n] : 0.0f;
        }
        __syncthreads();
#pragma unroll
        for (int kk = 0; kk < 8; kk++) {
            float a[8], bb[8];
            *reinterpret_cast<float4*>(a)      = *reinterpret_cast<const float4*>(&As[kk][trow]);
            *reinterpret_cast<float4*>(a + 4)  = *reinterpret_cast<const float4*>(&As[kk][trow + 4]);
            *reinterpret_cast<float4*>(bb)     = *reinterpret_cast<const float4*>(&Bs[kk][tcol]);
            *reinterpret_cast<float4*>(bb + 4) = *reinterpret_cast<const float4*>(&Bs[kk][tcol + 4]);
#pragma unroll
            for (int r = 0; r < 8; r++)
#pragma unroll
                for (int cc = 0; cc < 8; cc++)
                    acc[r][cc] = fmaf(a[r], bb[cc], acc[r][cc]);
        }
        __syncthreads();
    }
#pragma unroll
    for (int r = 0; r < 8; r++) {
        int row = m_base + trow + r;
        int tt = row >> 8, bb = row & 255;
#pragma unroll
        for (int cc = 0; cc < 8; cc++) {
            int n = n_base + tcol + cc;
            if (n < INF)
                out[(size_t)bb * (T_ * INF) + (size_t)tt * INF + n] = acc[r][cc] + bd[n];
        }
    }
}

// ---------------- launch ----------------
extern "C" void kernel_launch(void* const* d_in, const int* in_sizes, int n_in,
                              void* d_out, int out_size) {
    (void)in_sizes; (void)n_in; (void)out_size;
    const float* rs   = (const float*)d_in[0];
    const float* Wih1 = (const float*)d_in[1];
    const float* Whh1 = (const float*)d_in[2];
    const float* bih1 = (const float*)d_in[3];
    const float* bhh1 = (const float*)d_in[4];
    const float* Wih2 = (const float*)d_in[5];
    const float* Whh2 = (const float*)d_in[6];
    const float* bih2 = (const float*)d_in[7];
    const float* bhh2 = (const float*)d_in[8];
    const float* Wih3 = (const float*)d_in[9];
    const float* Whh3 = (const float*)d_in[10];
    const float* bih3 = (const float*)d_in[11];
    const float* bhh3 = (const float*)d_in[12];
    const float* Wd   = (const float*)d_in[13];
    const float* bd   = (const float*)d_in[14];
    float* out = (float*)d_out;

    cudaFuncSetAttribute(gates_kernel, cudaFuncAttributeMaxDynamicSharedMemorySize, DSMEM);

    k_zero<<<2048, 256>>>();
    k_setup<<<4096, 256>>>(Wih1, Whh1, Wih2, Whh2, Wih3, Whh3,
                           bih1, bhh1, bih2, bhh2, bih3, bhh3, Wd);
    k_setup_bd<<<(HID_ * INF + 255) / 256, 256>>>(Wd);

    for (int t = 0; t < T_; t++) {
        if ((t % 10) < 5)
            split_x<<<(B_ * INF + 255) / 256, 256>>>(rs, t);   // teacher forcing
        gates_kernel<<<dim3(32, 2, 3), 512, DSMEM>>>(t);
        if (t < T_ - 1 && ((t + 1) % 10) >= 5)
            feedback_kernel<<<64, 256>>>(t, bd);               // free-run input
    }
    dense_kernel<<<dim3(2, 200), 256>>>(out, bd);
}